// round 1
// baseline (speedup 1.0000x reference)
#include <cuda_runtime.h>
#include <math.h>
#include <stdint.h>

// Problem dims
#define BB 2048
#define SS 50
#define EE 256
#define HH 512
#define WW 256
#define LL 50
#define KCAT (EE + HH)   // 768
#define G4H  (4 * HH)    // 2048

// ---------------- device scratch (no allocations allowed) ----------------
__device__ float    g_xcat[BB * KCAT];        // [B, E+H] encoder step input
__device__ float    g_wcat[G4H * KCAT];       // [4H, E+H] = [enc_Wih | enc_Whh]
__device__ float    g_h[2][BB * HH];          // ping-pong hidden
__device__ float    g_c[2][BB * HH];          // ping-pong cell
__device__ float    g_gates[BB * G4H];        // GEMM output scratch
__device__ float    g_blend1[BB * SS * WW];   // [B,S,W]
__device__ float    g_blend2[BB * WW];        // [B,W]
__device__ float    g_gumbel[LL * BB * SS];   // precomputed gumbel noise
__device__ unsigned g_keys[2 * LL];           // threefry keys per decode step
__device__ int      g_mask[BB * SS];          // sampling mask (reset each call)

// ---------------- threefry2x32 (exact JAX implementation) ----------------
__device__ __forceinline__ unsigned rotl32(unsigned x, int d) {
    return (x << d) | (x >> (32 - d));
}

__device__ __forceinline__ void threefry2x32(unsigned k0, unsigned k1,
                                             unsigned x0, unsigned x1,
                                             unsigned& o0, unsigned& o1) {
    unsigned k2 = k0 ^ k1 ^ 0x1BD11BDAu;
    x0 += k0; x1 += k1;
#define TFR(r) { x0 += x1; x1 = rotl32(x1, r); x1 ^= x0; }
    TFR(13) TFR(15) TFR(26) TFR(6)   x0 += k1; x1 += k2 + 1u;
    TFR(17) TFR(29) TFR(16) TFR(24)  x0 += k2; x1 += k0 + 2u;
    TFR(13) TFR(15) TFR(26) TFR(6)   x0 += k0; x1 += k1 + 3u;
    TFR(17) TFR(29) TFR(16) TFR(24)  x0 += k1; x1 += k2 + 4u;
    TFR(13) TFR(15) TFR(26) TFR(6)   x0 += k2; x1 += k0 + 5u;
#undef TFR
    o0 = x0; o1 = x1;
}

// split(key(42), L) in fold-like (partitionable) mode: key_l = threefry(key, (0, l))
__global__ void keys_kernel(unsigned* keys) {
    int i = threadIdx.x;
    if (i < LL) {
        unsigned o0, o1;
        threefry2x32(0u, 42u, 0u, (unsigned)i, o0, o1);
        keys[2 * i]     = o0;
        keys[2 * i + 1] = o1;
    }
}

// partitionable random_bits (32-bit): bits[n] = o0 ^ o1, counts = (hi,lo) of 64-bit iota
__global__ void gumbel_kernel(const unsigned* __restrict__ keys, float* __restrict__ gout) {
    int idx = blockIdx.x * blockDim.x + threadIdx.x;
    if (idx >= LL * BB * SS) return;
    int l      = idx / (BB * SS);
    unsigned n = (unsigned)(idx % (BB * SS));
    unsigned o0, o1;
    threefry2x32(keys[2 * l], keys[2 * l + 1], 0u, n, o0, o1);
    unsigned bits = o0 ^ o1;
    float u = __uint_as_float((bits >> 9) | 0x3f800000u) - 1.0f;  // [0,1)
    if (u <= 0.0f) u = 1.17549435e-38f;                           // minval = tiny
    gout[idx] = -logf(-logf(u));
}

// ---------------- utility fills ----------------
__global__ void fill_f32(float* p, int n, float v) {
    int i = blockIdx.x * blockDim.x + threadIdx.x;
    if (i < n) p[i] = v;
}
__global__ void fill_i32(int* p, int n, int v) {
    int i = blockIdx.x * blockDim.x + threadIdx.x;
    if (i < n) p[i] = v;
}

// Wcat = [enc_Wih | enc_Whh] row-major [4H, E+H]
__global__ void build_wcat_kernel(const float* __restrict__ Wih,
                                  const float* __restrict__ Whh,
                                  float* __restrict__ wcat) {
    int idx = blockIdx.x * blockDim.x + threadIdx.x;
    if (idx >= G4H * KCAT) return;
    int n = idx / KCAT, k = idx % KCAT;
    wcat[idx] = (k < EE) ? Wih[n * EE + k] : Whh[n * HH + (k - EE)];
}

// xcat = [emb[input[:,t]] | h]  row-major [B, E+H]
__global__ void gather_xcat_kernel(const int* __restrict__ input,
                                   const float* __restrict__ emb,
                                   const float* __restrict__ h,
                                   float* __restrict__ xcat, int t) {
    int idx = blockIdx.x * blockDim.x + threadIdx.x;
    if (idx >= BB * KCAT) return;
    int b = idx / KCAT, k = idx % KCAT;
    float v;
    if (k < EE) v = emb[input[b * SS + t] * EE + k];
    else        v = h[b * HH + (k - EE)];
    xcat[idx] = v;
}

// ---------------- tiled SGEMM:  C[m,n] = sum_k A[m,k] * B[n,k]  (NT) ----------------
template <int BM, int BN, int BK, int TM, int TN, int NTHR>
__global__ __launch_bounds__(NTHR)
void sgemm_nt(const float* __restrict__ A, int lda,
              const float* __restrict__ Bw, int ldb,
              float* __restrict__ C, int ldc, int K) {
    static_assert(NTHR == (BM / TM) * (BN / TN), "thread count");
    static_assert(BM * BK / 4 == NTHR && BN * BK / 4 == NTHR, "one float4 per thread");
    const int bn = blockIdx.x * BN;
    const int bm = blockIdx.y * BM;
    __shared__ float As[BK][BM + 4];
    __shared__ float Bs[BK][BN + 4];
    const int tid = threadIdx.x;
    constexpr int NX = BN / TN;
    const int tx = tid % NX;
    const int ty = tid / NX;
    constexpr int K4 = BK / 4;
    const int lrow = tid / K4;
    const int lcol = (tid % K4) * 4;

    float acc[TM][TN];
#pragma unroll
    for (int i = 0; i < TM; i++)
#pragma unroll
        for (int j = 0; j < TN; j++) acc[i][j] = 0.0f;

    for (int k0 = 0; k0 < K; k0 += BK) {
        float4 va = *reinterpret_cast<const float4*>(&A[(size_t)(bm + lrow) * lda + k0 + lcol]);
        float4 vb = *reinterpret_cast<const float4*>(&Bw[(size_t)(bn + lrow) * ldb + k0 + lcol]);
        As[lcol + 0][lrow] = va.x; As[lcol + 1][lrow] = va.y;
        As[lcol + 2][lrow] = va.z; As[lcol + 3][lrow] = va.w;
        Bs[lcol + 0][lrow] = vb.x; Bs[lcol + 1][lrow] = vb.y;
        Bs[lcol + 2][lrow] = vb.z; Bs[lcol + 3][lrow] = vb.w;
        __syncthreads();
#pragma unroll
        for (int k = 0; k < BK; k++) {
            float ra[TM], rb[TN];
#pragma unroll
            for (int i = 0; i < TM; i += 4) {
                float4 v = *reinterpret_cast<const float4*>(&As[k][ty * TM + i]);
                ra[i] = v.x; ra[i + 1] = v.y; ra[i + 2] = v.z; ra[i + 3] = v.w;
            }
#pragma unroll
            for (int j = 0; j < TN; j += 4) {
                float4 v = *reinterpret_cast<const float4*>(&Bs[k][tx * TN + j]);
                rb[j] = v.x; rb[j + 1] = v.y; rb[j + 2] = v.z; rb[j + 3] = v.w;
            }
#pragma unroll
            for (int i = 0; i < TM; i++)
#pragma unroll
                for (int j = 0; j < TN; j++) acc[i][j] += ra[i] * rb[j];
        }
        __syncthreads();
    }
#pragma unroll
    for (int i = 0; i < TM; i++) {
        float* cp = &C[(size_t)(bm + ty * TM + i) * ldc + bn + tx * TN];
#pragma unroll
        for (int j = 0; j < TN; j += 4) {
            float4 v = make_float4(acc[i][j], acc[i][j + 1], acc[i][j + 2], acc[i][j + 3]);
            *reinterpret_cast<float4*>(cp + j) = v;
        }
    }
}

// ---------------- LSTM pointwise cell (torch gate order i,f,g,o) ----------------
__global__ void lstm_cell_kernel(const float* __restrict__ gates,
                                 const float* __restrict__ bih,
                                 const float* __restrict__ bhh,
                                 const float* __restrict__ c_in,
                                 float* __restrict__ h_out,
                                 float* __restrict__ c_out) {
    int idx = blockIdx.x * blockDim.x + threadIdx.x;
    if (idx >= BB * HH) return;
    int b = idx / HH, j = idx % HH;
    const float* g = gates + (size_t)b * G4H;
    float gi = g[j]          + (bih[j]          + bhh[j]);
    float gf = g[HH + j]     + (bih[HH + j]     + bhh[HH + j]);
    float gg = g[2 * HH + j] + (bih[2 * HH + j] + bhh[2 * HH + j]);
    float go = g[3 * HH + j] + (bih[3 * HH + j] + bhh[3 * HH + j]);
    float si = 1.0f / (1.0f + expf(-gi));
    float sf = 1.0f / (1.0f + expf(-gf));
    float so = 1.0f / (1.0f + expf(-go));
    float c = sf * c_in[idx] + si * tanhf(gg);
    c_out[idx] = c;
    h_out[idx] = so * tanhf(c);
}

// decoder init: h <- 0 (parity 1), c <- encoder final hidden (in parity 0)
__global__ void dec_init_kernel() {
    int idx = blockIdx.x * blockDim.x + threadIdx.x;
    if (idx >= BB * HH) return;
    g_h[1][idx] = 0.0f;
    g_c[1][idx] = g_h[0][idx];
}

// ---------------- attention scores + log_softmax + gumbel sample ----------------
__global__ __launch_bounds__(256)
void scores_kernel(const float* __restrict__ blend1, const float* __restrict__ blend2,
                   const float* __restrict__ vt, int* __restrict__ mask,
                   const float* __restrict__ gum, float* __restrict__ probs_out,
                   float* __restrict__ tour_out, int l) {
    int b = blockIdx.x;
    int tid = threadIdx.x, lane = tid & 31, warp = tid >> 5;
    __shared__ float sb2[WW];
    __shared__ float sv[WW];
    __shared__ float ssc[64];
    sb2[tid] = blend2[b * WW + tid];
    sv[tid]  = vt[tid];
    __syncthreads();

    // scores[s] = sum_w tanh(blend1[b,s,w] + blend2[b,w]) * vt[w]; masked -> -100000
    for (int s = warp; s < SS; s += 8) {
        const float* b1 = blend1 + ((size_t)b * SS + s) * WW;
        float p = 0.0f;
#pragma unroll
        for (int j = 0; j < WW / 32; j++) {
            int w = lane + 32 * j;
            p += tanhf(b1[w] + sb2[w]) * sv[w];
        }
#pragma unroll
        for (int off = 16; off; off >>= 1) p += __shfl_down_sync(0xffffffffu, p, off);
        if (lane == 0) ssc[s] = mask[b * SS + s] ? -100000.0f : p;
    }
    __syncthreads();

    if (warp == 0) {
        float v0 = (lane < SS)      ? ssc[lane]      : -INFINITY;
        float v1 = (lane + 32 < SS) ? ssc[lane + 32] : -INFINITY;
        float mx = fmaxf(v0, v1);
#pragma unroll
        for (int off = 16; off; off >>= 1) mx = fmaxf(mx, __shfl_xor_sync(0xffffffffu, mx, off));
        float e0 = (lane < SS)      ? expf(v0 - mx) : 0.0f;
        float e1 = (lane + 32 < SS) ? expf(v1 - mx) : 0.0f;
        float sum = e0 + e1;
#pragma unroll
        for (int off = 16; off; off >>= 1) sum += __shfl_xor_sync(0xffffffffu, sum, off);
        float lse = logf(sum);

        float best = -INFINITY; int bidx = 0;
        if (lane < SS) {
            float lp = (v0 - mx) - lse;
            probs_out[((size_t)b * LL + l) * SS + lane] = lp;
            best = lp + gum[b * SS + lane];
            bidx = lane;
        }
        if (lane + 32 < SS) {
            float lp = (v1 - mx) - lse;
            probs_out[((size_t)b * LL + l) * SS + lane + 32] = lp;
            float t = lp + gum[b * SS + lane + 32];
            if (t > best) { best = t; bidx = lane + 32; }  // strict > keeps first max
        }
#pragma unroll
        for (int off = 16; off; off >>= 1) {
            float ob = __shfl_down_sync(0xffffffffu, best, off);
            int   oi = __shfl_down_sync(0xffffffffu, bidx, off);
            if (ob > best || (ob == best && oi < bidx)) { best = ob; bidx = oi; }
        }
        if (lane == 0) {
            mask[b * SS + bidx] = 1;
            if (tour_out) tour_out[(size_t)b * LL + l] = (float)bidx;
        }
    }
}

// ---------------- host driver (graph-capturable: kernels only) ----------------
extern "C" void kernel_launch(void* const* d_in, const int* in_sizes, int n_in,
                              void* d_out, int out_size) {
    const int*   input   = (const int*)d_in[0];
    const float* emb     = (const float*)d_in[1];
    const float* enc_Wih = (const float*)d_in[2];
    const float* enc_Whh = (const float*)d_in[3];
    const float* enc_bih = (const float*)d_in[4];
    const float* enc_bhh = (const float*)d_in[5];
    // d_in[6] = dec_Wih: unused (decoder input is always zero in the reference)
    const float* dec_Whh = (const float*)d_in[7];
    const float* dec_bih = (const float*)d_in[8];
    const float* dec_bhh = (const float*)d_in[9];
    const float* W1      = (const float*)d_in[10];
    const float* W2      = (const float*)d_in[11];
    const float* vt      = (const float*)d_in[12];
    float* out = (float*)d_out;

    float *xcat, *wcat, *hbuf, *cbuf, *gates, *b1, *b2, *gum;
    int* mask; unsigned* keys;
    cudaGetSymbolAddress((void**)&xcat,  g_xcat);
    cudaGetSymbolAddress((void**)&wcat,  g_wcat);
    cudaGetSymbolAddress((void**)&hbuf,  g_h);
    cudaGetSymbolAddress((void**)&cbuf,  g_c);
    cudaGetSymbolAddress((void**)&gates, g_gates);
    cudaGetSymbolAddress((void**)&b1,    g_blend1);
    cudaGetSymbolAddress((void**)&b2,    g_blend2);
    cudaGetSymbolAddress((void**)&gum,   g_gumbel);
    cudaGetSymbolAddress((void**)&keys,  g_keys);
    cudaGetSymbolAddress((void**)&mask,  g_mask);
    float* h0 = hbuf;            float* h1 = hbuf + (size_t)BB * HH;
    float* c0 = cbuf;            float* c1 = cbuf + (size_t)BB * HH;

    const int NBH = (BB * HH + 255) / 256;

    // setup (re-done every call -> deterministic under graph replay)
    fill_f32<<<NBH, 256>>>(h0, BB * HH, 0.0f);
    fill_f32<<<NBH, 256>>>(c0, BB * HH, 0.0f);
    fill_i32<<<(BB * SS + 255) / 256, 256>>>(mask, BB * SS, 0);
    build_wcat_kernel<<<(G4H * KCAT + 255) / 256, 256>>>(enc_Wih, enc_Whh, wcat);
    keys_kernel<<<1, 64>>>(keys);
    gumbel_kernel<<<(LL * BB * SS + 255) / 256, 256>>>(keys, gum);

    // ---------------- encoder ----------------
    for (int t = 0; t < SS; t++) {
        const float* hin  = (t & 1) ? h1 : h0;
        const float* cin  = (t & 1) ? c1 : c0;
        float*       hout = (t & 1) ? h0 : h1;
        float*       cout = (t & 1) ? c0 : c1;
        gather_xcat_kernel<<<(BB * KCAT + 255) / 256, 256>>>(input, emb, hin, xcat, t);
        sgemm_nt<128, 128, 8, 8, 8, 256>
            <<<dim3(G4H / 128, BB / 128), 256>>>(xcat, KCAT, wcat, KCAT, gates, G4H, KCAT);
        lstm_cell_kernel<<<NBH, 256>>>(gates, enc_bih, enc_bhh, cin, hout, cout);
        // blend1[:, t, :] = h_t @ W1^T
        sgemm_nt<64, 64, 16, 4, 4, 256>
            <<<dim3(WW / 64, BB / 64), 256>>>(hout, HH, W1, HH, b1 + t * WW, SS * WW, HH);
    }
    // encoder final hidden lands in parity 0 (t=49 writes h0)
    dec_init_kernel<<<NBH, 256>>>();  // h1 <- 0, c1 <- h0

    float* tour = ((size_t)out_size >= (size_t)BB * LL * SS + (size_t)BB * LL)
                      ? out + (size_t)BB * LL * SS : nullptr;

    // ---------------- decoder ----------------
    for (int l = 0; l < LL; l++) {
        const float* hin  = (l & 1) ? h0 : h1;
        const float* cin  = (l & 1) ? c0 : c1;
        float*       hout = (l & 1) ? h1 : h0;
        float*       cout = (l & 1) ? c1 : c0;
        // gates = h @ dec_Whh^T   (decoder input is zero -> no Wih term)
        sgemm_nt<128, 128, 8, 8, 8, 256>
            <<<dim3(G4H / 128, BB / 128), 256>>>(hin, HH, dec_Whh, HH, gates, G4H, HH);
        lstm_cell_kernel<<<NBH, 256>>>(gates, dec_bih, dec_bhh, cin, hout, cout);
        // blend2 = h @ W2^T
        sgemm_nt<64, 64, 16, 4, 4, 256>
            <<<dim3(WW / 64, BB / 64), 256>>>(hout, HH, W2, HH, b2, WW, HH);
        scores_kernel<<<BB, 256>>>(b1, b2, vt, mask, gum + (size_t)l * BB * SS, out, tour, l);
    }
    (void)in_sizes; (void)n_in;
}

// round 8
// speedup vs baseline: 1.3865x; 1.3865x over previous
#include <cuda_runtime.h>
#include <math.h>
#include <stdint.h>

// Problem dims
#define BB 2048
#define SS 50
#define EE 256
#define HH 512
#define WW 256
#define LL 50
#define VV 51
#define G4H  (4 * HH)    // 2048

// ---------------- device scratch (no allocations allowed) ----------------
__device__ __align__(128) float    g_wpe[G4H * HH];          // enc Whh, gate-interleaved rows
__device__ __align__(128) float    g_wpd[G4H * HH];          // dec Whh, gate-interleaved rows
__device__ __align__(128) float    g_embw[VV * G4H];         // emb @ enc_Wih^T, gate-interleaved cols
__device__ __align__(128) float    g_bse[G4H];               // enc bih+bhh, permuted
__device__ __align__(128) float    g_bsd[G4H];               // dec bih+bhh, permuted
__device__ __align__(128) float    g_encst[BB * SS * HH];    // encoder hidden states [B,S,H]
__device__ __align__(128) float    g_h[2][BB * HH];          // decoder ping-pong hidden (+enc h0 zeros)
__device__ __align__(128) float    g_c[2][BB * HH];          // ping-pong cell
__device__ __align__(128) float    g_blend1[BB * SS * WW];   // [B,S,W]
__device__ __align__(128) float    g_blend2[BB * WW];        // [B,W]
__device__ __align__(128) float    g_gumbel[LL * BB * SS];   // precomputed gumbel noise
__device__ __align__(128) unsigned g_keys[2 * LL];           // threefry keys per decode step
__device__ __align__(128) int      g_mask[BB * SS];          // sampling mask (reset each call)

// ---------------- threefry2x32 (exact JAX implementation) ----------------
__device__ __forceinline__ unsigned rotl32(unsigned x, int d) {
    return (x << d) | (x >> (32 - d));
}

__device__ __forceinline__ void threefry2x32(unsigned k0, unsigned k1,
                                             unsigned x0, unsigned x1,
                                             unsigned& o0, unsigned& o1) {
    unsigned k2 = k0 ^ k1 ^ 0x1BD11BDAu;
    x0 += k0; x1 += k1;
#define TFR(r) { x0 += x1; x1 = rotl32(x1, r); x1 ^= x0; }
    TFR(13) TFR(15) TFR(26) TFR(6)   x0 += k1; x1 += k2 + 1u;
    TFR(17) TFR(29) TFR(16) TFR(24)  x0 += k2; x1 += k0 + 2u;
    TFR(13) TFR(15) TFR(26) TFR(6)   x0 += k0; x1 += k1 + 3u;
    TFR(17) TFR(29) TFR(16) TFR(24)  x0 += k1; x1 += k2 + 4u;
    TFR(13) TFR(15) TFR(26) TFR(6)   x0 += k2; x1 += k0 + 5u;
#undef TFR
    o0 = x0; o1 = x1;
}

// setup launch #0: zero h0, c0, mask
__global__ void init_state_kernel() {
    int i = blockIdx.x * blockDim.x + threadIdx.x;
    if (i < BB * HH) { g_h[0][i] = 0.0f; g_c[0][i] = 0.0f; }
    if (i < BB * SS) g_mask[i] = 0;
}

// setup launch #1: split(key(42), L), fold-like mode: key_l = threefry(key, (0, l))
__global__ void keys_kernel(unsigned* keys) {
    int i = threadIdx.x;
    if (i < LL) {
        unsigned o0, o1;
        threefry2x32(0u, 42u, 0u, (unsigned)i, o0, o1);
        keys[2 * i]     = o0;
        keys[2 * i + 1] = o1;
    }
}

// setup launch #2: partitionable random_bits (32-bit): bits[n] = o0 ^ o1
__global__ void gumbel_kernel(const unsigned* __restrict__ keys, float* __restrict__ gout) {
    int idx = blockIdx.x * blockDim.x + threadIdx.x;
    if (idx >= LL * BB * SS) return;
    int l      = idx / (BB * SS);
    unsigned n = (unsigned)(idx % (BB * SS));
    unsigned o0, o1;
    threefry2x32(keys[2 * l], keys[2 * l + 1], 0u, n, o0, o1);
    unsigned bits = o0 ^ o1;
    float u = __uint_as_float((bits >> 9) | 0x3f800000u) - 1.0f;  // [0,1)
    if (u <= 0.0f) u = 1.17549435e-38f;                           // minval = tiny
    gout[idx] = -logf(-logf(u));
}

// setup launch #3: gate-interleave permutation of both Whh matrices + bias sums.
// perm row n = 4*j + g  <-  original row g*H + j   (torch gate order i,f,g,o)
__global__ void perm_kernel(const float* __restrict__ eWhh, const float* __restrict__ dWhh,
                            const float* __restrict__ ebih, const float* __restrict__ ebhh,
                            const float* __restrict__ dbih, const float* __restrict__ dbhh) {
    int idx = blockIdx.x * blockDim.x + threadIdx.x;
    if (idx >= G4H * HH) return;
    int n = idx / HH, k = idx % HH;
    int j = n >> 2, g = n & 3;
    int src = (g * HH + j) * HH + k;
    g_wpe[idx] = eWhh[src];
    g_wpd[idx] = dWhh[src];
    if (k == 0) {
        g_bse[n] = ebih[g * HH + j] + ebhh[g * HH + j];
        g_bsd[n] = dbih[g * HH + j] + dbhh[g * HH + j];
    }
}

// setup launch #4: embW[v][4j+g] = sum_e emb[v,e] * enc_Wih[g*H+j, e]
__global__ __launch_bounds__(256)
void embw_kernel(const float* __restrict__ emb, const float* __restrict__ Wih) {
    __shared__ float se[EE];
    int v = blockIdx.x;
    int tid = threadIdx.x;
    se[tid] = emb[v * EE + tid];
    __syncthreads();
#pragma unroll
    for (int q = 0; q < G4H / 256; q++) {
        int n = tid + q * 256;
        int j = n >> 2, g = n & 3;
        const float* wr = Wih + (size_t)(g * HH + j) * EE;
        float s = 0.0f;
#pragma unroll 8
        for (int e = 0; e < EE; e++) s += se[e] * wr[e];
        g_embw[(size_t)v * G4H + n] = s;
    }
}

__device__ __forceinline__ float sigf(float x) { return 1.0f / (1.0f + expf(-x)); }

// ---------------- fused LSTM step: gates = A @ Wp^T (+embW row) -> cell -> h,c ------
// A: h_in [B,H] row stride lda_a; Wp: [4H(perm), H]; embp: [V,4H(perm)] or null;
// h_out row stride ld_h. 128x128 tile, BK=8 double-buffered, 8x8/thread, 256 thr.
__global__ __launch_bounds__(256)
void lstm_step_kernel(const float* __restrict__ A, int lda_a,
                      const float* __restrict__ Wp,
                      const float* __restrict__ embp,
                      const int* __restrict__ input, int t,
                      const float* __restrict__ bsum,
                      const float* __restrict__ c_in,
                      float* __restrict__ h_out, int ld_h,
                      float* __restrict__ c_out) {
    const int bn = blockIdx.x * 128;
    const int bm = blockIdx.y * 128;
    __shared__ float As[2][8][132];
    __shared__ float Bs[2][8][132];
    const int tid = threadIdx.x;
    const int tx = tid % 16, ty = tid / 16;
    const int lrow = tid >> 1, lcol = (tid & 1) * 4;

    const float* aptr = A  + (size_t)(bm + lrow) * lda_a + lcol;
    const float* bptr = Wp + (size_t)(bn + lrow) * HH + lcol;

    float acc[8][8];
#pragma unroll
    for (int i = 0; i < 8; i++)
#pragma unroll
        for (int j = 0; j < 8; j++) acc[i][j] = 0.0f;

    float4 va = *(const float4*)aptr;
    float4 vb = *(const float4*)bptr;
    As[0][lcol + 0][lrow] = va.x; As[0][lcol + 1][lrow] = va.y;
    As[0][lcol + 2][lrow] = va.z; As[0][lcol + 3][lrow] = va.w;
    Bs[0][lcol + 0][lrow] = vb.x; Bs[0][lcol + 1][lrow] = vb.y;
    Bs[0][lcol + 2][lrow] = vb.z; Bs[0][lcol + 3][lrow] = vb.w;
    __syncthreads();

    int buf = 0;
    const int NKT = HH / 8;  // 64
    for (int kt = 0; kt < NKT; kt++) {
        if (kt < NKT - 1) {
            va = *(const float4*)(aptr + (kt + 1) * 8);
            vb = *(const float4*)(bptr + (kt + 1) * 8);
        }
#pragma unroll
        for (int k = 0; k < 8; k++) {
            float4 a0 = *(const float4*)&As[buf][k][ty * 8];
            float4 a1 = *(const float4*)&As[buf][k][ty * 8 + 4];
            float4 b0 = *(const float4*)&Bs[buf][k][tx * 8];
            float4 b1 = *(const float4*)&Bs[buf][k][tx * 8 + 4];
            float ra[8] = {a0.x, a0.y, a0.z, a0.w, a1.x, a1.y, a1.z, a1.w};
            float rb[8] = {b0.x, b0.y, b0.z, b0.w, b1.x, b1.y, b1.z, b1.w};
#pragma unroll
            for (int i = 0; i < 8; i++)
#pragma unroll
                for (int j = 0; j < 8; j++) acc[i][j] += ra[i] * rb[j];
        }
        if (kt < NKT - 1) {
            int nb = buf ^ 1;
            As[nb][lcol + 0][lrow] = va.x; As[nb][lcol + 1][lrow] = va.y;
            As[nb][lcol + 2][lrow] = va.z; As[nb][lcol + 3][lrow] = va.w;
            Bs[nb][lcol + 0][lrow] = vb.x; Bs[nb][lcol + 1][lrow] = vb.y;
            Bs[nb][lcol + 2][lrow] = vb.z; Bs[nb][lcol + 3][lrow] = vb.w;
            __syncthreads();
            buf = nb;
        }
    }

    // ---- fused epilogue: biases (+ optional embW gather) -> LSTM cell -> h,c ----
    const int n0 = bn + tx * 8;          // 8 consecutive perm-gate cols = 2 j-groups
    const int j0 = n0 >> 2;
    float4 bs0 = *(const float4*)&bsum[n0];
    float4 bs1 = *(const float4*)&bsum[n0 + 4];
#pragma unroll
    for (int i = 0; i < 8; i++) {
        int b = bm + ty * 8 + i;
        float q0 = acc[i][0] + bs0.x, q1 = acc[i][1] + bs0.y;
        float q2 = acc[i][2] + bs0.z, q3 = acc[i][3] + bs0.w;
        float q4 = acc[i][4] + bs1.x, q5 = acc[i][5] + bs1.y;
        float q6 = acc[i][6] + bs1.z, q7 = acc[i][7] + bs1.w;
        if (embp != nullptr) {
            const float* er = embp + (size_t)input[b * SS + t] * G4H + n0;
            float4 e0 = *(const float4*)er;
            float4 e1 = *(const float4*)(er + 4);
            q0 += e0.x; q1 += e0.y; q2 += e0.z; q3 += e0.w;
            q4 += e1.x; q5 += e1.y; q6 += e1.z; q7 += e1.w;
        }
        float2 cp = *(const float2*)&c_in[(size_t)b * HH + j0];
        // gate order within group: i,f,g,o
        float cA = sigf(q1) * cp.x + sigf(q0) * tanhf(q2);
        float hA = sigf(q3) * tanhf(cA);
        float cB = sigf(q5) * cp.y + sigf(q4) * tanhf(q6);
        float hB = sigf(q7) * tanhf(cB);
        *(float2*)&c_out[(size_t)b * HH + j0] = make_float2(cA, cB);
        *(float2*)&h_out[(size_t)b * ld_h + j0] = make_float2(hA, hB);
    }
}

// ---------------- tiled SGEMM (NT) for the blend projections ----------------
template <int BM, int BN, int BK, int TM, int TN, int NTHR>
__global__ __launch_bounds__(NTHR)
void sgemm_nt(const float* __restrict__ A, int lda,
              const float* __restrict__ Bw, int ldb,
              float* __restrict__ C, int ldc, int K) {
    static_assert(NTHR == (BM / TM) * (BN / TN), "thread count");
    static_assert(BM * BK / 4 == NTHR && BN * BK / 4 == NTHR, "one float4 per thread");
    const int bn = blockIdx.x * BN;
    const int bm = blockIdx.y * BM;
    __shared__ float As[BK][BM + 4];
    __shared__ float Bs[BK][BN + 4];
    const int tid = threadIdx.x;
    constexpr int NX = BN / TN;
    const int tx = tid % NX;
    const int ty = tid / NX;
    constexpr int K4 = BK / 4;
    const int lrow = tid / K4;
    const int lcol = (tid % K4) * 4;

    float acc[TM][TN];
#pragma unroll
    for (int i = 0; i < TM; i++)
#pragma unroll
        for (int j = 0; j < TN; j++) acc[i][j] = 0.0f;

    for (int k0 = 0; k0 < K; k0 += BK) {
        float4 va = *reinterpret_cast<const float4*>(&A[(size_t)(bm + lrow) * lda + k0 + lcol]);
        float4 vb = *reinterpret_cast<const float4*>(&Bw[(size_t)(bn + lrow) * ldb + k0 + lcol]);
        As[lcol + 0][lrow] = va.x; As[lcol + 1][lrow] = va.y;
        As[lcol + 2][lrow] = va.z; As[lcol + 3][lrow] = va.w;
        Bs[lcol + 0][lrow] = vb.x; Bs[lcol + 1][lrow] = vb.y;
        Bs[lcol + 2][lrow] = vb.z; Bs[lcol + 3][lrow] = vb.w;
        __syncthreads();
#pragma unroll
        for (int k = 0; k < BK; k++) {
            float ra[TM], rb[TN];
#pragma unroll
            for (int i = 0; i < TM; i += 4) {
                float4 v = *reinterpret_cast<const float4*>(&As[k][ty * TM + i]);
                ra[i] = v.x; ra[i + 1] = v.y; ra[i + 2] = v.z; ra[i + 3] = v.w;
            }
#pragma unroll
            for (int j = 0; j < TN; j += 4) {
                float4 v = *reinterpret_cast<const float4*>(&Bs[k][tx * TN + j]);
                rb[j] = v.x; rb[j + 1] = v.y; rb[j + 2] = v.z; rb[j + 3] = v.w;
            }
#pragma unroll
            for (int i = 0; i < TM; i++)
#pragma unroll
                for (int j = 0; j < TN; j++) acc[i][j] += ra[i] * rb[j];
        }
        __syncthreads();
    }
#pragma unroll
    for (int i = 0; i < TM; i++) {
        float* cp = &C[(size_t)(bm + ty * TM + i) * ldc + bn + tx * TN];
#pragma unroll
        for (int j = 0; j < TN; j += 4) {
            float4 v = make_float4(acc[i][j], acc[i][j + 1], acc[i][j + 2], acc[i][j + 3]);
            *reinterpret_cast<float4*>(cp + j) = v;
        }
    }
}

// decoder init: h[1] <- 0, c[1] <- encoder final hidden enc_states[:,S-1,:]
__global__ void dec_init_kernel() {
    int idx = blockIdx.x * blockDim.x + threadIdx.x;
    if (idx >= BB * HH) return;
    int b = idx / HH, j = idx % HH;
    g_h[1][idx] = 0.0f;
    g_c[1][idx] = g_encst[(size_t)b * SS * HH + (SS - 1) * HH + j];
}

// ---------------- attention scores + log_softmax + gumbel sample ----------------
__global__ __launch_bounds__(256)
void scores_kernel(const float* __restrict__ blend1, const float* __restrict__ blend2,
                   const float* __restrict__ vt, int* __restrict__ mask,
                   const float* __restrict__ gum, float* __restrict__ probs_out,
                   float* __restrict__ tour_out, int l) {
    int b = blockIdx.x;
    int tid = threadIdx.x, lane = tid & 31, warp = tid >> 5;
    __shared__ float sb2[WW];
    __shared__ float sv[WW];
    __shared__ float ssc[64];
    sb2[tid] = blend2[b * WW + tid];
    sv[tid]  = vt[tid];
    __syncthreads();

    for (int s = warp; s < SS; s += 8) {
        const float* b1 = blend1 + ((size_t)b * SS + s) * WW;
        float p = 0.0f;
#pragma unroll
        for (int j = 0; j < WW / 32; j++) {
            int w = lane + 32 * j;
            p += tanhf(b1[w] + sb2[w]) * sv[w];
        }
#pragma unroll
        for (int off = 16; off; off >>= 1) p += __shfl_down_sync(0xffffffffu, p, off);
        if (lane == 0) ssc[s] = mask[b * SS + s] ? -100000.0f : p;
    }
    __syncthreads();

    if (warp == 0) {
        float v0 = (lane < SS)      ? ssc[lane]      : -INFINITY;
        float v1 = (lane + 32 < SS) ? ssc[lane + 32] : -INFINITY;
        float mx = fmaxf(v0, v1);
#pragma unroll
        for (int off = 16; off; off >>= 1) mx = fmaxf(mx, __shfl_xor_sync(0xffffffffu, mx, off));
        float e0 = (lane < SS)      ? expf(v0 - mx) : 0.0f;
        float e1 = (lane + 32 < SS) ? expf(v1 - mx) : 0.0f;
        float sum = e0 + e1;
#pragma unroll
        for (int off = 16; off; off >>= 1) sum += __shfl_xor_sync(0xffffffffu, sum, off);
        float lse = logf(sum);

        float best = -INFINITY; int bidx = 0;
        if (lane < SS) {
            float lp = (v0 - mx) - lse;
            probs_out[((size_t)b * LL + l) * SS + lane] = lp;
            best = lp + gum[b * SS + lane];
            bidx = lane;
        }
        if (lane + 32 < SS) {
            float lp = (v1 - mx) - lse;
            probs_out[((size_t)b * LL + l) * SS + lane + 32] = lp;
            float tt = lp + gum[b * SS + lane + 32];
            if (tt > best) { best = tt; bidx = lane + 32; }  // strict > keeps first max
        }
#pragma unroll
        for (int off = 16; off; off >>= 1) {
            float ob = __shfl_down_sync(0xffffffffu, best, off);
            int   oi = __shfl_down_sync(0xffffffffu, bidx, off);
            if (ob > best || (ob == best && oi < bidx)) { best = ob; bidx = oi; }
        }
        if (lane == 0) {
            mask[b * SS + bidx] = 1;
            if (tour_out) tour_out[(size_t)b * LL + l] = (float)bidx;
        }
    }
}

// ---------------- host driver (graph-capturable: kernels only) ----------------
extern "C" void kernel_launch(void* const* d_in, const int* in_sizes, int n_in,
                              void* d_out, int out_size) {
    const int*   input   = (const int*)d_in[0];
    const float* emb     = (const float*)d_in[1];
    const float* enc_Wih = (const float*)d_in[2];
    const float* enc_Whh = (const float*)d_in[3];
    const float* enc_bih = (const float*)d_in[4];
    const float* enc_bhh = (const float*)d_in[5];
    // d_in[6] = dec_Wih: unused (decoder input is always zero in the reference)
    const float* dec_Whh = (const float*)d_in[7];
    const float* dec_bih = (const float*)d_in[8];
    const float* dec_bhh = (const float*)d_in[9];
    const float* W1      = (const float*)d_in[10];
    const float* W2      = (const float*)d_in[11];
    const float* vt      = (const float*)d_in[12];
    float* out = (float*)d_out;

    float *hbuf, *cbuf, *b1, *b2, *gum, *embw, *wpe, *wpd, *bse, *bsd, *encst;
    int* mask; unsigned* keys;
    cudaGetSymbolAddress((void**)&hbuf, g_h);
    cudaGetSymbolAddress((void**)&cbuf, g_c);
    cudaGetSymbolAddress((void**)&b1,   g_blend1);
    cudaGetSymbolAddress((void**)&b2,   g_blend2);
    cudaGetSymbolAddress((void**)&gum,  g_gumbel);
    cudaGetSymbolAddress((void**)&keys, g_keys);
    cudaGetSymbolAddress((void**)&mask, g_mask);
    cudaGetSymbolAddress((void**)&embw, g_embw);
    cudaGetSymbolAddress((void**)&wpe,  g_wpe);
    cudaGetSymbolAddress((void**)&wpd,  g_wpd);
    cudaGetSymbolAddress((void**)&bse,  g_bse);
    cudaGetSymbolAddress((void**)&bsd,  g_bsd);
    cudaGetSymbolAddress((void**)&encst, g_encst);
    float* h0 = hbuf;            float* h1 = hbuf + (size_t)BB * HH;
    float* c0 = cbuf;            float* c1 = cbuf + (size_t)BB * HH;

    const int NBH = (BB * HH + 255) / 256;
    const dim3 ggrid(G4H / 128, BB / 128);

    // setup — ordered so launch index 5 (ncu -s 5 -c 1) is the first fused GEMM
    init_state_kernel<<<NBH, 256>>>();                                        // 0
    keys_kernel<<<1, 64>>>(keys);                                             // 1
    gumbel_kernel<<<(LL * BB * SS + 255) / 256, 256>>>(keys, gum);            // 2
    perm_kernel<<<(G4H * HH + 255) / 256, 256>>>(enc_Whh, dec_Whh,            // 3
                                                 enc_bih, enc_bhh, dec_bih, dec_bhh);
    embw_kernel<<<VV, 256>>>(emb, enc_Wih);                                   // 4

    // ---------------- encoder (h states written strided into enc_states) ---------
    for (int t = 0; t < SS; t++) {
        const float* hin  = (t == 0) ? h0 : (encst + (size_t)(t - 1) * HH);
        const int    lda  = (t == 0) ? HH : SS * HH;
        const float* cin  = (t & 1) ? c1 : c0;
        float*       cout = (t & 1) ? c0 : c1;
        float*       hout = encst + (size_t)t * HH;
        lstm_step_kernel<<<ggrid, 256>>>(hin, lda, wpe, embw, input, t, bse,
                                         cin, hout, SS * HH, cout);
    }
    dec_init_kernel<<<NBH, 256>>>();  // h1 <- 0, c1 <- enc_states[:,S-1,:]

    // ONE batched blend1 GEMM: [B*S, W] = enc_states[B*S, H] @ W1^T
    sgemm_nt<128, 128, 8, 8, 8, 256>
        <<<dim3(WW / 128, BB * SS / 128), 256>>>(encst, HH, W1, HH, b1, WW, HH);

    float* tour = ((size_t)out_size >= (size_t)BB * LL * SS + (size_t)BB * LL)
                      ? out + (size_t)BB * LL * SS : nullptr;

    // ---------------- decoder ----------------
    for (int l = 0; l < LL; l++) {
        const float* hin  = (l & 1) ? h0 : h1;
        const float* cin  = (l & 1) ? c0 : c1;
        float*       hout = (l & 1) ? h1 : h0;
        float*       cout = (l & 1) ? c1 : c0;
        // decoder input is zero -> gates = h @ dec_Whh^T + biases only
        lstm_step_kernel<<<ggrid, 256>>>(hin, HH, wpd, nullptr, nullptr, 0, bsd,
                                         cin, hout, HH, cout);
        // blend2 = h @ W2^T
        sgemm_nt<64, 64, 16, 4, 4, 256>
            <<<dim3(WW / 64, BB / 64), 256>>>(hout, HH, W2, HH, b2, WW, HH);
        scores_kernel<<<BB, 256>>>(b1, b2, vt, mask, gum + (size_t)l * BB * SS, out, tour, l);
    }
    (void)in_sizes; (void)n_in;
}